// round 9
// baseline (speedup 1.0000x reference)
#include <cuda_runtime.h>
#include <cuda_bf16.h>

#define IW 1920
#define IH 1080
#define BXT 32            // threads x
#define BYT 8             // threads y
#define NTH (BXT * BYT)   // 256
#define NG 3              // row-groups per block (sequential)
#define TPW 128           // tile pixel width (32 thr * 4 px)
#define TPH (BYT * NG)    // 24 pixel rows per block
#define SMW 136           // floats per smem row: 4 pad + 128 + 4 pad
#define SMH (TPH + 6)     // 30 rows incl. halo
#define NF4 ((SMW / 4) * SMH)  // 34 * 30 = 1020

__device__ __forceinline__ unsigned mul2k(unsigned v, unsigned k) {
    // Force IMAD (fma pipe) instead of SHF/LEA (alu pipe).
    unsigned t;
    asm("mul.lo.u32 %0, %1, %2;" : "=r"(t) : "r"(v), "r"(k));
    return t;
}

__device__ __forceinline__ unsigned fold9(unsigned b) {
    // 24-bit circular buffer = bytes [b0, b1, b0, 0] via one PRMT.
    // LEFT-shift run-length fold (shift = IMAD on fma pipe, AND = LOP3 on alu):
    // result bit i set <=> bits i-8..i all set (9-run ending at i). Upper byte
    // of the buffer is 0, so no false positives past bit 23.
    unsigned v = __byte_perm(b, 0, 0x4010);
    v &= mul2k(v, 2u);    // runs >= 2
    v &= mul2k(v, 4u);    // runs >= 4
    v &= mul2k(v, 16u);   // runs >= 8
    v &= mul2k(v, 2u);    // runs >= 9
    return v;
}

// Compute one row-group (4 horizontally adjacent pixels per thread) and store.
__device__ __forceinline__ void compute_group(
        const float* __restrict__ sm, float* __restrict__ om,
        int gi, int bx, int by) {
    const int pr = gi * BYT + threadIdx.y;              // pixel row in tile
    const int basei = (pr + 3) * SMW + threadIdx.x * 4 + 4;

    float w[12], c[4];
    unsigned dk[4] = {0u, 0u, 0u, 0u};
    unsigned br[4] = {0u, 0u, 0u, 0u};

    // w[j] = value at column x0 + j - 4 of row (pr + 3 + dy).
    #define LOADROW(dy) {                                                   \
        const float4* p = (const float4*)(sm + basei + (dy) * SMW - 4);     \
        float4 A = p[0], B = p[1], C = p[2];                                \
        w[0]=A.x; w[1]=A.y; w[2]=A.z;  w[3]=A.w;                            \
        w[4]=B.x; w[5]=B.y; w[6]=B.z;  w[7]=B.w;                            \
        w[8]=C.x; w[9]=C.y; w[10]=C.z; w[11]=C.w; }

    // Same fp op order as reference: d = circle - center; d>=20 / d<=-20.
    // set.{ge,le}.u32.f32 -> FSET: all-ones/zero register (no predicate
    // guard latency); merge is a single LOP3: dk |= s & (1<<bit).
    #define CMP(i, dx, bit) {                                               \
        float d = w[(i) + 4 + (dx)] - c[i];                                 \
        unsigned sd, sb;                                                    \
        asm("set.ge.u32.f32 %0, %1, %2;" : "=r"(sd) : "f"(d), "f"(20.0f)); \
        asm("set.le.u32.f32 %0, %1, %2;" : "=r"(sb) : "f"(d), "f"(-20.0f));\
        dk[i] |= sd & (1u << (bit));                                        \
        br[i] |= sb & (1u << (bit)); }

    #define ROW2(dxa, ba, dxb, bb)                                          \
        _Pragma("unroll") for (int i = 0; i < 4; i++) {                     \
            CMP(i, dxa, ba) CMP(i, dxb, bb) }
    #define ROW3(dxa, ba, dxb, bb, dxc, bc)                                 \
        _Pragma("unroll") for (int i = 0; i < 4; i++) {                     \
            CMP(i, dxa, ba) CMP(i, dxb, bb) CMP(i, dxc, bc) }

    LOADROW(0);
    c[0] = w[4]; c[1] = w[5]; c[2] = w[6]; c[3] = w[7];
    ROW2(-3, 0,  3, 8);                     // (0,-3)->0, (0,3)->8
    LOADROW(-3); ROW3(-1, 13, 0, 12, 1, 11);
    LOADROW(-2); ROW2(-2, 14, 2, 10);
    LOADROW(-1); ROW2(-3, 15, 3,  9);
    LOADROW( 1); ROW2(-3,  1, 3,  7);
    LOADROW( 2); ROW2(-2,  2, 2,  6);
    LOADROW( 3); ROW3(-1,  3, 0,  4, 1, 5);

    #undef LOADROW
    #undef CMP
    #undef ROW2
    #undef ROW3

    float4 r;
    r.x = (fold9(dk[0]) | fold9(br[0])) ? 1.0f : 0.0f;
    r.y = (fold9(dk[1]) | fold9(br[1])) ? 1.0f : 0.0f;
    r.z = (fold9(dk[2]) | fold9(br[2])) ? 1.0f : 0.0f;
    r.w = (fold9(dk[3]) | fold9(br[3])) ? 1.0f : 0.0f;

    const int y = by + pr;
    *(float4*)(om + (size_t)y * IW + bx + threadIdx.x * 4) = r;
}

__global__ __launch_bounds__(NTH)
void fast_score_kernel(const float* __restrict__ img,
                       float* __restrict__ out) {
    __shared__ __align__(16) float sm[SMH * SMW];

    const int n = blockIdx.z;
    const float* im = img + (size_t)n * (IH * IW);
    float* om = out + (size_t)n * (IH * IW);

    const int bx = blockIdx.x * TPW;
    const int by = blockIdx.y * TPH;
    const int tid = threadIdx.y * BXT + threadIdx.x;

    const bool interior = (blockIdx.x > 0) & (blockIdx.x < gridDim.x - 1) &
                          (blockIdx.y > 0) & (blockIdx.y < gridDim.y - 1);

    if (interior) {
        // Tile covers rows by-3..by+26, cols bx-4..bx+131, all in-bounds,
        // 16B-aligned (bx % 128 == 0). Pure LDG.128/STS.128 fill.
        const float4* g = (const float4*)(im + (size_t)(by - 3) * IW + (bx - 4));
        #pragma unroll
        for (int k = 0; k < 4; k++) {
            int i = tid + k * NTH;
            if (i < NF4) {
                int ly = i / 34;
                int kx = i - ly * 34;
                ((float4*)sm)[i] = g[ly * (IW / 4) + kx];
            }
        }
    } else {
        // Boundary blocks: scalar fill with replicate clamp.
        for (int e = tid; e < SMH * SMW; e += NTH) {
            int ly = e / SMW;
            int lx = e - ly * SMW;
            int gy = min(max(by + ly - 3, 0), IH - 1);
            int gx = min(max(bx + lx - 4, 0), IW - 1);
            sm[e] = __ldg(&im[(size_t)gy * IW + gx]);
        }
    }
    __syncthreads();

    #pragma unroll 1
    for (int gi = 0; gi < NG; gi++) {
        compute_group(sm, om, gi, bx, by);
    }
}

extern "C" void kernel_launch(void* const* d_in, const int* in_sizes, int n_in,
                              void* d_out, int out_size) {
    const float* img = (const float*)d_in[0];
    float* out = (float*)d_out;
    const int N = in_sizes[0] / (IH * IW);

    dim3 block(BXT, BYT, 1);
    dim3 grid(IW / TPW, IH / TPH, N);   // 15 x 45 x N (exact)
    fast_score_kernel<<<grid, block>>>(img, out);
}

// round 10
// speedup vs baseline: 1.5195x; 1.5195x over previous
#include <cuda_runtime.h>
#include <cuda_bf16.h>

#define IW 1920
#define IH 1080
#define BXT 32            // threads x
#define BYT 8             // threads y
#define NTH (BXT * BYT)   // 256
#define NG 3              // row-groups per block (sequential)
#define TPW 128           // tile pixel width (32 thr * 4 px)
#define TPH (BYT * NG)    // 24 pixel rows per block
#define SMW 136           // floats per smem row: 4 pad + 128 + 4 pad
#define SMH (TPH + 6)     // 30 rows incl. halo
#define QPR (SMW / 4)     // 34 quads per smem row
#define NQ_A (14 * QPR)   // rows 0..13  (group 0 needs these)
#define NQ_B (22 * QPR)   // rows 0..21
#define NQ_C (30 * QPR)   // rows 0..29

__device__ __forceinline__ void cp_async16(unsigned saddr, const void* gptr) {
    asm volatile("cp.async.cg.shared.global [%0], [%1], 16;"
                 :: "r"(saddr), "l"(gptr));
}
__device__ __forceinline__ void cp_commit() {
    asm volatile("cp.async.commit_group;");
}
template <int N>
__device__ __forceinline__ void cp_wait() {
    asm volatile("cp.async.wait_group %0;" :: "n"(N));
}

// 9-consecutive-set-bits test over a circular 16-bit mask held in the low
// (sel=0x4010) or high (sel=0x4232) half of m. PRMT builds the 24-bit ring
// buffer [b_lo, b_hi, b_lo, 0]; run-length fold; bits >=16 self-zero.
template <unsigned SEL>
__device__ __forceinline__ unsigned fold9(unsigned m) {
    unsigned v = __byte_perm(m, 0, SEL);
    v &= v >> 1;   // runs >= 2
    v &= v >> 2;   // runs >= 4
    v &= v >> 4;   // runs >= 8
    v &= v >> 1;   // runs >= 9
    return v;
}

// Compute one row-group (4 horizontally adjacent pixels per thread) and store.
__device__ __forceinline__ void compute_group(
        const float* __restrict__ sm, float* __restrict__ om,
        int gi, int bx, int by) {
    const int pr = gi * BYT + threadIdx.y;              // pixel row in tile
    const int basei = (pr + 3) * SMW + threadIdx.x * 4 + 4;

    float w[12], c[4];
    // Combined masks: dark bit k at position k, bright bit k at position k+16.
    unsigned m[4] = {0u, 0u, 0u, 0u};

    // w[j] = value at column x0 + j - 4 of row (pr + 3 + dy).
    #define LOADROW(dy) {                                                   \
        const float4* p = (const float4*)(sm + basei + (dy) * SMW - 4);     \
        float4 A = p[0], B = p[1], C = p[2];                                \
        w[0]=A.x; w[1]=A.y; w[2]=A.z;  w[3]=A.w;                            \
        w[4]=B.x; w[5]=B.y; w[6]=B.z;  w[7]=B.w;                            \
        w[8]=C.x; w[9]=C.y; w[10]=C.z; w[11]=C.w; }

    // Same fp op order as reference: d = circle - center; d>=20 / d<=-20.
    #define CMP(i, dx, bit) {                                               \
        float d = w[(i) + 4 + (dx)] - c[i];                                 \
        if (d >=  20.0f) m[i] |= (1u << (bit));                             \
        if (d <= -20.0f) m[i] |= (0x10000u << (bit)); }
    #define ROW2(dxa, ba, dxb, bb)                                          \
        _Pragma("unroll") for (int i = 0; i < 4; i++) {                     \
            CMP(i, dxa, ba) CMP(i, dxb, bb) }
    #define ROW3(dxa, ba, dxb, bb, dxc, bc)                                 \
        _Pragma("unroll") for (int i = 0; i < 4; i++) {                     \
            CMP(i, dxa, ba) CMP(i, dxb, bb) CMP(i, dxc, bc) }

    LOADROW(0);
    c[0] = w[4]; c[1] = w[5]; c[2] = w[6]; c[3] = w[7];
    ROW2(-3, 0,  3, 8);                     // (0,-3)->0, (0,3)->8
    LOADROW(-3); ROW3(-1, 13, 0, 12, 1, 11);
    LOADROW(-2); ROW2(-2, 14, 2, 10);
    LOADROW(-1); ROW2(-3, 15, 3,  9);
    LOADROW( 1); ROW2(-3,  1, 3,  7);
    LOADROW( 2); ROW2(-2,  2, 2,  6);
    LOADROW( 3); ROW3(-1,  3, 0,  4, 1, 5);

    #undef LOADROW
    #undef CMP
    #undef ROW2
    #undef ROW3

    float4 r;
    r.x = (fold9<0x4010>(m[0]) | fold9<0x4232>(m[0])) ? 1.0f : 0.0f;
    r.y = (fold9<0x4010>(m[1]) | fold9<0x4232>(m[1])) ? 1.0f : 0.0f;
    r.z = (fold9<0x4010>(m[2]) | fold9<0x4232>(m[2])) ? 1.0f : 0.0f;
    r.w = (fold9<0x4010>(m[3]) | fold9<0x4232>(m[3])) ? 1.0f : 0.0f;

    const int y = by + pr;
    *(float4*)(om + (size_t)y * IW + bx + threadIdx.x * 4) = r;
}

__global__ __launch_bounds__(NTH, 8)   // pin regs <= 32: no occupancy cliff
void fast_score_kernel(const float* __restrict__ img,
                       float* __restrict__ out) {
    __shared__ __align__(16) float sm[SMH * SMW];

    const int n = blockIdx.z;
    const float* im = img + (size_t)n * (IH * IW);
    float* om = out + (size_t)n * (IH * IW);

    const int bx = blockIdx.x * TPW;
    const int by = blockIdx.y * TPH;
    const int tid = threadIdx.y * BXT + threadIdx.x;

    const bool interior = (blockIdx.x > 0) & (blockIdx.x < gridDim.x - 1) &
                          (blockIdx.y > 0) & (blockIdx.y < gridDim.y - 1);

    if (interior) {
        // Tile rows by-3..by+26, cols bx-4..bx+131 all in-bounds, 16B aligned
        // (bx % 128 == 0). Three cp.async stages issued up front; progressive
        // waits overlap later stages' DRAM latency with group 0/1 compute.
        const unsigned sbase = (unsigned)__cvta_generic_to_shared(sm);
        const float4* g = (const float4*)(im + (size_t)(by - 3) * IW + (bx - 4));

        #pragma unroll
        for (int k = 0; k < 2; k++) {                 // stage A: rows 0..13
            int i = tid + k * NTH;
            if (i < NQ_A) {
                int r = i / QPR, cq = i - r * QPR;
                cp_async16(sbase + i * 16, g + (size_t)r * (IW / 4) + cq);
            }
        }
        cp_commit();
        #pragma unroll
        for (int k = 0; k < 2; k++) {                 // stage B: rows 14..21
            int i = NQ_A + tid + k * NTH;
            if (i < NQ_B) {
                int r = i / QPR, cq = i - r * QPR;
                cp_async16(sbase + i * 16, g + (size_t)r * (IW / 4) + cq);
            }
        }
        cp_commit();
        #pragma unroll
        for (int k = 0; k < 2; k++) {                 // stage C: rows 22..29
            int i = NQ_B + tid + k * NTH;
            if (i < NQ_C) {
                int r = i / QPR, cq = i - r * QPR;
                cp_async16(sbase + i * 16, g + (size_t)r * (IW / 4) + cq);
            }
        }
        cp_commit();

        cp_wait<2>();        // stage A resident
        __syncthreads();
        compute_group(sm, om, 0, bx, by);

        cp_wait<1>();        // stages A+B resident
        __syncthreads();
        compute_group(sm, om, 1, bx, by);

        cp_wait<0>();        // all resident
        __syncthreads();
        compute_group(sm, om, 2, bx, by);
    } else {
        // Boundary blocks: scalar fill with replicate clamp, then compute.
        for (int e = tid; e < SMH * SMW; e += NTH) {
            int ly = e / SMW;
            int lx = e - ly * SMW;
            int gy = min(max(by + ly - 3, 0), IH - 1);
            int gx = min(max(bx + lx - 4, 0), IW - 1);
            sm[e] = __ldg(&im[(size_t)gy * IW + gx]);
        }
        __syncthreads();
        #pragma unroll 1
        for (int gi = 0; gi < NG; gi++) {
            compute_group(sm, om, gi, bx, by);
        }
    }
}

extern "C" void kernel_launch(void* const* d_in, const int* in_sizes, int n_in,
                              void* d_out, int out_size) {
    const float* img = (const float*)d_in[0];
    float* out = (float*)d_out;
    const int N = in_sizes[0] / (IH * IW);

    dim3 block(BXT, BYT, 1);
    dim3 grid(IW / TPW, IH / TPH, N);   // 15 x 45 x N (exact)
    fast_score_kernel<<<grid, block>>>(img, out);
}

// round 13
// speedup vs baseline: 1.5918x; 1.0476x over previous
#include <cuda_runtime.h>
#include <cuda_bf16.h>

#define IW 1920
#define IH 1080
#define BXT 32            // threads x
#define BYT 8             // threads y
#define NTH (BXT * BYT)   // 256
#define NG 3              // row-groups per block (sequential)
#define TPW 128           // tile pixel width (32 thr * 4 px)
#define TPH (BYT * NG)    // 24 pixel rows per block
#define SMW 136           // floats per smem row: 4 pad + 128 + 4 pad
#define SMH (TPH + 6)     // 30 rows incl. halo
#define NF4 ((SMW / 4) * SMH)  // 34 * 30 = 1020

// Dual-ring circular 9-run test. m holds TWO interleaved 16-bit rings:
// dark bit k at position 2k, bright bit k at position 2k+1. A 32-bit
// rotate-right by 2 (one SHF.R.W32) rotates BOTH rings by one step with
// correct circular wraparound. Fold shifts 1+2+4+1 ring-steps => runs >= 9.
// Nonzero result <=> a 9-run exists in either ring.
__device__ __forceinline__ unsigned rotfold9(unsigned v) {
    v &= __funnelshift_r(v, v, 2);   // runs >= 2 (ring step 1)
    v &= __funnelshift_r(v, v, 4);   // runs >= 4
    v &= __funnelshift_r(v, v, 8);   // runs >= 8
    v &= __funnelshift_r(v, v, 2);   // runs >= 9
    return v;
}

// Compute one row-group (4 horizontally adjacent pixels per thread) and store.
__device__ __forceinline__ void compute_group(
        const float* __restrict__ sm, float* __restrict__ om,
        int gi, int bx, int by) {
    const int pr = gi * BYT + threadIdx.y;              // pixel row in tile
    const int basei = (pr + 3) * SMW + threadIdx.x * 4 + 4;

    float w[12], c[4];
    unsigned m[4] = {0u, 0u, 0u, 0u};   // interleaved dark/bright rings

    // w[j] = value at column x0 + j - 4 of row (pr + 3 + dy).
    #define LOADROW(dy) {                                                   \
        const float4* p = (const float4*)(sm + basei + (dy) * SMW - 4);     \
        float4 A = p[0], B = p[1], C = p[2];                                \
        w[0]=A.x; w[1]=A.y; w[2]=A.z;  w[3]=A.w;                            \
        w[4]=B.x; w[5]=B.y; w[6]=B.z;  w[7]=B.w;                            \
        w[8]=C.x; w[9]=C.y; w[10]=C.z; w[11]=C.w; }

    // Same fp op order as reference: d = circle - center; d>=20 / d<=-20.
    // dark -> even bit 2k, bright -> odd bit 2k+1 (immediates fold into LOP3).
    #define CMP(i, dx, bit) {                                               \
        float d = w[(i) + 4 + (dx)] - c[i];                                 \
        if (d >=  20.0f) m[i] |= (1u << (2 * (bit)));                       \
        if (d <= -20.0f) m[i] |= (2u << (2 * (bit))); }
    #define ROW2(dxa, ba, dxb, bb)                                          \
        _Pragma("unroll") for (int i = 0; i < 4; i++) {                     \
            CMP(i, dxa, ba) CMP(i, dxb, bb) }
    #define ROW3(dxa, ba, dxb, bb, dxc, bc)                                 \
        _Pragma("unroll") for (int i = 0; i < 4; i++) {                     \
            CMP(i, dxa, ba) CMP(i, dxb, bb) CMP(i, dxc, bc) }

    LOADROW(0);
    c[0] = w[4]; c[1] = w[5]; c[2] = w[6]; c[3] = w[7];
    ROW2(-3, 0,  3, 8);                     // (0,-3)->0, (0,3)->8
    LOADROW(-3); ROW3(-1, 13, 0, 12, 1, 11);
    LOADROW(-2); ROW2(-2, 14, 2, 10);
    LOADROW(-1); ROW2(-3, 15, 3,  9);
    LOADROW( 1); ROW2(-3,  1, 3,  7);
    LOADROW( 2); ROW2(-2,  2, 2,  6);
    LOADROW( 3); ROW3(-1,  3, 0,  4, 1, 5);

    #undef LOADROW
    #undef CMP
    #undef ROW2
    #undef ROW3

    float4 r;
    r.x = rotfold9(m[0]) ? 1.0f : 0.0f;
    r.y = rotfold9(m[1]) ? 1.0f : 0.0f;
    r.z = rotfold9(m[2]) ? 1.0f : 0.0f;
    r.w = rotfold9(m[3]) ? 1.0f : 0.0f;

    const int y = by + pr;
    *(float4*)(om + (size_t)y * IW + bx + threadIdx.x * 4) = r;
}

__global__ __launch_bounds__(NTH, 8)   // pin regs <= 32: no occupancy cliff
void fast_score_kernel(const float* __restrict__ img,
                       float* __restrict__ out) {
    __shared__ __align__(16) float sm[SMH * SMW];

    const int n = blockIdx.z;
    const float* im = img + (size_t)n * (IH * IW);
    float* om = out + (size_t)n * (IH * IW);

    const int bx = blockIdx.x * TPW;
    const int by = blockIdx.y * TPH;
    const int tid = threadIdx.y * BXT + threadIdx.x;

    const bool interior = (blockIdx.x > 0) & (blockIdx.x < gridDim.x - 1) &
                          (blockIdx.y > 0) & (blockIdx.y < gridDim.y - 1);

    if (interior) {
        // Tile covers rows by-3..by+26, cols bx-4..bx+131, all in-bounds,
        // 16B-aligned (bx % 128 == 0). Pure LDG.128/STS.128 fill.
        const float4* g = (const float4*)(im + (size_t)(by - 3) * IW + (bx - 4));
        #pragma unroll
        for (int k = 0; k < 4; k++) {
            int i = tid + k * NTH;
            if (i < NF4) {
                int ly = i / 34;
                int kx = i - ly * 34;
                ((float4*)sm)[i] = g[ly * (IW / 4) + kx];
            }
        }
    } else {
        // Boundary blocks: scalar fill with replicate clamp.
        for (int e = tid; e < SMH * SMW; e += NTH) {
            int ly = e / SMW;
            int lx = e - ly * SMW;
            int gy = min(max(by + ly - 3, 0), IH - 1);
            int gx = min(max(bx + lx - 4, 0), IW - 1);
            sm[e] = __ldg(&im[(size_t)gy * IW + gx]);
        }
    }
    __syncthreads();

    #pragma unroll 1
    for (int gi = 0; gi < NG; gi++) {
        compute_group(sm, om, gi, bx, by);
    }
}

extern "C" void kernel_launch(void* const* d_in, const int* in_sizes, int n_in,
                              void* d_out, int out_size) {
    const float* img = (const float*)d_in[0];
    float* out = (float*)d_out;
    const int N = in_sizes[0] / (IH * IW);

    dim3 block(BXT, BYT, 1);
    dim3 grid(IW / TPW, IH / TPH, N);   // 15 x 45 x N (exact)
    fast_score_kernel<<<grid, block>>>(img, out);
}